// round 3
// baseline (speedup 1.0000x reference)
#include <cuda_runtime.h>
#include <math.h>

// Problem constants (from reference): C=64 channels, H=2 heads, L=3 layers.
// N and E are taken from in_sizes at runtime; static scratch sized generously.
#define C 64
#define NHEADS 2
#define NLAYERS 3
#define MAX_N 65536
#define MAX_ETOT 2000000
#define SLOPE 0.2f

// ---------------- device scratch (no allocation allowed) ----------------
__device__ int   g_deg[MAX_N];
__device__ int   g_incl[MAX_N];
__device__ int   g_bsum[256];
__device__ int   g_rowptr[MAX_N + 1];
__device__ int   g_fillptr[MAX_N];
__device__ int   g_col[MAX_ETOT];
__device__ float g_buf0[(size_t)MAX_N * C];
__device__ float g_buf1[(size_t)MAX_N * C];
__device__ float g_accum[(size_t)MAX_N * C];

// ---------------- CSR build ----------------

// deg[i] = 1 initially (the self loop contributes 1 to every node)
__global__ void k_init_deg(int n) {
    int i = blockIdx.x * blockDim.x + threadIdx.x;
    if (i < n) g_deg[i] = 1;
}

__global__ void k_count(const int* __restrict__ ei, int E) {
    int i = blockIdx.x * blockDim.x + threadIdx.x;
    if (i < E) atomicAdd(&g_deg[ei[E + i]], 1);   // dst row of edge_index
}

// per-block inclusive scan (1024 elems/block)
__global__ void k_scan_block(int n) {
    __shared__ int sh[1024];
    int i = blockIdx.x * 1024 + threadIdx.x;
    int v = (i < n) ? g_deg[i] : 0;
    sh[threadIdx.x] = v;
    __syncthreads();
    #pragma unroll
    for (int off = 1; off < 1024; off <<= 1) {
        int t = (threadIdx.x >= off) ? sh[threadIdx.x - off] : 0;
        __syncthreads();
        sh[threadIdx.x] += t;
        __syncthreads();
    }
    if (i < n) g_incl[i] = sh[threadIdx.x];
    if (threadIdx.x == 1023) g_bsum[blockIdx.x] = sh[1023];
}

// exclusive scan of block sums (tiny: <=64 blocks)
__global__ void k_scan_bsum(int nb) {
    if (threadIdx.x == 0 && blockIdx.x == 0) {
        int acc = 0;
        for (int b = 0; b < nb; ++b) { int t = g_bsum[b]; g_bsum[b] = acc; acc += t; }
    }
}

__global__ void k_rowptr(int n, int etot) {
    int i = blockIdx.x * blockDim.x + threadIdx.x;
    if (i < n) {
        int ex = g_incl[i] - g_deg[i] + g_bsum[i >> 10];  // exclusive prefix
        g_rowptr[i] = ex;
        g_fillptr[i] = ex;
    }
    if (i == 0) g_rowptr[n] = etot;
}

__global__ void k_fill(const int* __restrict__ ei, int E, int n) {
    int i = blockIdx.x * blockDim.x + threadIdx.x;
    int tot = E + n;
    if (i >= tot) return;
    int src, dst;
    if (i < E) { src = ei[i]; dst = ei[E + i]; }
    else       { src = dst = i - E; }              // self loop
    int pos = atomicAdd(&g_fillptr[dst], 1);
    g_col[pos] = src;
}

// ---------------- feature init / finalize ----------------

__global__ void k_init_accum(const float* __restrict__ x, int total) {
    int i = blockIdx.x * blockDim.x + threadIdx.x;
    if (i < total) g_accum[i] = x[i];
}

__global__ void k_finalize(float* __restrict__ out, int total) {
    int i = blockIdx.x * blockDim.x + threadIdx.x;
    if (i < total) out[i] = g_accum[i] * 0.25f;   // mean over [x, h1, h2, h3]
}

// ---------------- GAT layer: one warp per destination node ----------------
// Online (running-max) softmax over incoming edges, both heads in parallel.
// Each lane owns channels {2*lane, 2*lane+1}.
__global__ void k_gat(const float* __restrict__ x,
                      float* __restrict__ nxt,
                      const float* __restrict__ att,    // [2,64] for this layer
                      const float* __restrict__ bias,   // [64]
                      int n) {
    int node = blockIdx.x * (blockDim.x >> 5) + (threadIdx.x >> 5);
    if (node >= n) return;
    int lane = threadIdx.x & 31;

    // attention vectors, 2 channels per lane per head
    float a00 = att[2 * lane],       a01 = att[2 * lane + 1];
    float a10 = att[C + 2 * lane],   a11 = att[C + 2 * lane + 1];

    float2 xd = *(const float2*)(x + (size_t)node * C + 2 * lane);

    float m0 = -INFINITY, m1 = -INFINITY;   // running max per head
    float s0 = 0.f, s1 = 0.f;               // running denom per head
    float ax0 = 0.f, ay0 = 0.f;             // running numerator (2 channels) head0
    float ax1 = 0.f, ay1 = 0.f;             // head1

    int beg = g_rowptr[node];
    int end = g_rowptr[node + 1];

    for (int e = beg; e < end; ++e) {
        int src = g_col[e];
        float2 xs = *(const float2*)(x + (size_t)src * C + 2 * lane);

        float t0 = xd.x + xs.x; t0 = (t0 > 0.f) ? t0 : SLOPE * t0;
        float t1 = xd.y + xs.y; t1 = (t1 > 0.f) ? t1 : SLOPE * t1;

        float p0 = fmaf(t0, a00, t1 * a01);
        float p1 = fmaf(t0, a10, t1 * a11);
        #pragma unroll
        for (int o = 16; o > 0; o >>= 1) {
            p0 += __shfl_xor_sync(0xffffffffu, p0, o);
            p1 += __shfl_xor_sync(0xffffffffu, p1, o);
        }

        // online softmax update, head 0
        float nm0 = fmaxf(m0, p0);
        float c0  = __expf(m0 - nm0);
        float w0  = __expf(p0 - nm0);
        s0  = fmaf(s0, c0, w0);
        ax0 = fmaf(ax0, c0, w0 * xs.x);
        ay0 = fmaf(ay0, c0, w0 * xs.y);
        m0 = nm0;

        // head 1
        float nm1 = fmaxf(m1, p1);
        float c1  = __expf(m1 - nm1);
        float w1  = __expf(p1 - nm1);
        s1  = fmaf(s1, c1, w1);
        ax1 = fmaf(ax1, c1, w1 * xs.x);
        ay1 = fmaf(ay1, c1, w1 * xs.y);
        m1 = nm1;
    }

    float inv0 = 1.f / (s0 + 1e-16f);
    float inv1 = 1.f / (s1 + 1e-16f);
    float rx = 0.5f * (ax0 * inv0 + ax1 * inv1) + bias[2 * lane];
    float ry = 0.5f * (ay0 * inv0 + ay1 * inv1) + bias[2 * lane + 1];

    size_t o = (size_t)node * C + 2 * lane;
    nxt[o]     = rx;
    nxt[o + 1] = ry;
    g_accum[o]     += rx;
    g_accum[o + 1] += ry;
}

// ---------------- host launcher ----------------
extern "C" void kernel_launch(void* const* d_in, const int* in_sizes, int n_in,
                              void* d_out, int out_size) {
    const float* x    = (const float*)d_in[0];   // [N, 64]
    const int*   ei   = (const int*)d_in[1];     // [2, E]
    const float* att  = (const float*)d_in[2];   // [L, 2, 64]
    const float* bias = (const float*)d_in[3];   // [L, 64]
    float* out = (float*)d_out;

    int n    = in_sizes[0] / C;
    int E    = in_sizes[1] / 2;
    int etot = E + n;
    int total = n * C;

    float *buf0, *buf1;
    cudaGetSymbolAddress((void**)&buf0, g_buf0);
    cudaGetSymbolAddress((void**)&buf1, g_buf1);

    const int T = 256;
    // ---- CSR build ----
    k_init_deg<<<(n + T - 1) / T, T>>>(n);
    k_count<<<(E + T - 1) / T, T>>>(ei, E);
    int nb = (n + 1023) / 1024;
    k_scan_block<<<nb, 1024>>>(n);
    k_scan_bsum<<<1, 32>>>(nb);
    k_rowptr<<<(n + T - 1) / T, T>>>(n, etot);
    k_fill<<<(etot + T - 1) / T, T>>>(ei, E, n);

    // ---- accum = x ----
    k_init_accum<<<(total + T - 1) / T, T>>>(x, total);

    // ---- 3 GAT layers (8 warps per block, warp per node) ----
    int gb = (n + 7) / 8;
    k_gat<<<gb, 256>>>(x,    buf0, att,           bias,           n);
    k_gat<<<gb, 256>>>(buf0, buf1, att + 2 * C,   bias + C,       n);
    k_gat<<<gb, 256>>>(buf1, buf0, att + 4 * C,   bias + 2 * C,   n);

    // ---- out = accum / 4 ----
    k_finalize<<<(total + T - 1) / T, T>>>(out, total);
}

// round 6
// speedup vs baseline: 1.5065x; 1.5065x over previous
#include <cuda_runtime.h>
#include <math.h>

#define C 64
#define NLAYERS 3
#define MAX_N 65536
#define MAX_ETOT 2000000
#define SLOPE 0.2f

// ---------------- device scratch (no allocation allowed) ----------------
__device__ int   g_deg[MAX_N];
__device__ int   g_incl[MAX_N];
__device__ int   g_bsum[256];
__device__ int   g_rowptr[MAX_N + 1];
__device__ int   g_fillptr[MAX_N];
__device__ int   g_col[MAX_ETOT];
__device__ float g_buf0[(size_t)MAX_N * C];
__device__ float g_buf1[(size_t)MAX_N * C];
__device__ float g_accum[(size_t)MAX_N * C];

// ---------------- CSR build ----------------

__global__ void k_init_deg(int n) {
    int i = blockIdx.x * blockDim.x + threadIdx.x;
    if (i < n) g_deg[i] = 1;                      // self loop
}

__global__ void k_count(const int* __restrict__ ei, int E) {
    int i = blockIdx.x * blockDim.x + threadIdx.x;
    if (i < E) atomicAdd(&g_deg[ei[E + i]], 1);   // dst row
}

// per-block inclusive scan (1024 elems/block)
__global__ void k_scan_block(int n) {
    __shared__ int sh[1024];
    int i = blockIdx.x * 1024 + threadIdx.x;
    int v = (i < n) ? g_deg[i] : 0;
    sh[threadIdx.x] = v;
    __syncthreads();
    #pragma unroll
    for (int off = 1; off < 1024; off <<= 1) {
        int t = (threadIdx.x >= off) ? sh[threadIdx.x - off] : 0;
        __syncthreads();
        sh[threadIdx.x] += t;
        __syncthreads();
    }
    if (i < n) g_incl[i] = sh[threadIdx.x];
    if (threadIdx.x == 1023) g_bsum[blockIdx.x] = sh[1023];
}

// parallel exclusive scan of block sums (nb <= 64)
__global__ void k_scan_bsum(int nb) {
    __shared__ int sh[64];
    int t = threadIdx.x;
    int v = (t < nb) ? g_bsum[t] : 0;
    sh[t] = v;
    __syncthreads();
    #pragma unroll
    for (int off = 1; off < 64; off <<= 1) {
        int u = (t >= off) ? sh[t - off] : 0;
        __syncthreads();
        sh[t] += u;
        __syncthreads();
    }
    if (t < nb) g_bsum[t] = sh[t] - v;            // exclusive
}

__global__ void k_rowptr(int n, int etot) {
    int i = blockIdx.x * blockDim.x + threadIdx.x;
    if (i < n) {
        int ex = g_incl[i] - g_deg[i] + g_bsum[i >> 10];
        g_rowptr[i] = ex;
        g_fillptr[i] = ex;
    }
    if (i == 0) g_rowptr[n] = etot;
}

__global__ void k_fill(const int* __restrict__ ei, int E, int n) {
    int i = blockIdx.x * blockDim.x + threadIdx.x;
    int tot = E + n;
    if (i >= tot) return;
    int src, dst;
    if (i < E) { src = ei[i]; dst = ei[E + i]; }
    else       { src = dst = i - E; }
    int pos = atomicAdd(&g_fillptr[dst], 1);
    g_col[pos] = src;
}

// ---------------- GAT layer: one warp per destination node ----------------
// No max-subtraction (scores are O(1); exp() is safe in fp32 — identical math
// up to rounding). Half-warp dual reduction: lanes 0-15 reduce head0's dot,
// lanes 16-31 head1's → 7 SHFL + 1 expf per edge (vs 10 SHFL + 4 expf).
// mode: 0 = first layer (accum = x + r), 1 = middle (accum += r),
//       2 = last (out = (accum + r) * 0.25)
__global__ void k_gat(const float* __restrict__ x,
                      float* __restrict__ nxt,
                      float* __restrict__ out,
                      const float* __restrict__ att,    // [2,64] this layer
                      const float* __restrict__ bias,   // [64]
                      int n, int mode) {
    int node = blockIdx.x * (blockDim.x >> 5) + (threadIdx.x >> 5);
    if (node >= n) return;
    int lane = threadIdx.x & 31;
    const unsigned FULL = 0xffffffffu;

    float a00 = att[2 * lane],     a01 = att[2 * lane + 1];      // head 0
    float a10 = att[C + 2 * lane], a11 = att[C + 2 * lane + 1];  // head 1

    float2 xd = *(const float2*)(x + (size_t)node * C + 2 * lane);

    float s_mine = 0.f;                      // head (lane>=16) denom
    float ax0 = 0.f, ay0 = 0.f;              // head0 numerator (2 channels)
    float ax1 = 0.f, ay1 = 0.f;              // head1

    int beg = g_rowptr[node];
    int end = g_rowptr[node + 1];

    #pragma unroll 2
    for (int e = beg; e < end; ++e) {
        int src = g_col[e];
        float2 xs = *(const float2*)(x + (size_t)src * C + 2 * lane);

        float t0 = xd.x + xs.x; t0 = (t0 > 0.f) ? t0 : SLOPE * t0;
        float t1 = xd.y + xs.y; t1 = (t1 > 0.f) ? t1 : SLOPE * t1;

        float p0 = fmaf(t0, a00, t1 * a01);  // head0 partial (2 channels)
        float p1 = fmaf(t0, a10, t1 * a11);  // head1 partial

        // fold heads into warp halves, then 4-step butterfly within halves
        float pa = __shfl_xor_sync(FULL, p0, 16);
        float pb = __shfl_xor_sync(FULL, p1, 16);
        float v = (lane < 16) ? (p0 + pa) : (p1 + pb);
        #pragma unroll
        for (int o = 8; o > 0; o >>= 1)
            v += __shfl_xor_sync(FULL, v, o);
        // lanes 0-15: full head0 score; lanes 16-31: full head1 score

        float w_mine = __expf(v);
        float w_oth  = __shfl_xor_sync(FULL, w_mine, 16);
        float w0 = (lane < 16) ? w_mine : w_oth;
        float w1 = (lane < 16) ? w_oth  : w_mine;

        s_mine += w_mine;
        ax0 = fmaf(w0, xs.x, ax0);
        ay0 = fmaf(w0, xs.y, ay0);
        ax1 = fmaf(w1, xs.x, ax1);
        ay1 = fmaf(w1, xs.y, ay1);
    }

    float s0 = __shfl_sync(FULL, s_mine, 0);
    float s1 = __shfl_sync(FULL, s_mine, 16);
    float inv0 = 1.f / (s0 + 1e-16f);
    float inv1 = 1.f / (s1 + 1e-16f);

    float rx = 0.5f * fmaf(ax0, inv0, ax1 * inv1) + bias[2 * lane];
    float ry = 0.5f * fmaf(ay0, inv0, ay1 * inv1) + bias[2 * lane + 1];

    size_t o = (size_t)node * C + 2 * lane;
    if (mode == 2) {
        float2 acc = *(const float2*)(g_accum + o);
        float2 res; res.x = (acc.x + rx) * 0.25f; res.y = (acc.y + ry) * 0.25f;
        *(float2*)(out + o) = res;
    } else {
        float2 nv; nv.x = rx; nv.y = ry;
        *(float2*)(nxt + o) = nv;
        float2 acc;
        if (mode == 0) { acc.x = xd.x + rx; acc.y = xd.y + ry; }
        else {
            acc = *(const float2*)(g_accum + o);
            acc.x += rx; acc.y += ry;
        }
        *(float2*)(g_accum + o) = acc;
    }
}

// ---------------- host launcher ----------------
extern "C" void kernel_launch(void* const* d_in, const int* in_sizes, int n_in,
                              void* d_out, int out_size) {
    const float* x    = (const float*)d_in[0];   // [N, 64]
    const int*   ei   = (const int*)d_in[1];     // [2, E]
    const float* att  = (const float*)d_in[2];   // [L, 2, 64]
    const float* bias = (const float*)d_in[3];   // [L, 64]
    float* out = (float*)d_out;

    int n    = in_sizes[0] / C;
    int E    = in_sizes[1] / 2;
    int etot = E + n;

    float *buf0, *buf1;
    cudaGetSymbolAddress((void**)&buf0, g_buf0);
    cudaGetSymbolAddress((void**)&buf1, g_buf1);

    const int T = 256;
    // ---- CSR build ----
    k_init_deg<<<(n + T - 1) / T, T>>>(n);
    k_count<<<(E + T - 1) / T, T>>>(ei, E);
    int nb = (n + 1023) / 1024;
    k_scan_block<<<nb, 1024>>>(n);
    k_scan_bsum<<<1, 64>>>(nb);
    k_rowptr<<<(n + T - 1) / T, T>>>(n, etot);
    k_fill<<<(etot + T - 1) / T, T>>>(ei, E, n);

    // ---- 3 GAT layers (8 warps/block, warp per node); accum fused ----
    int gb = (n + 7) / 8;
    k_gat<<<gb, 256>>>(x,    buf0, out, att,         bias,         n, 0);
    k_gat<<<gb, 256>>>(buf0, buf1, out, att + 2 * C, bias + C,     n, 1);
    k_gat<<<gb, 256>>>(buf1, buf0, out, att + 4 * C, bias + 2 * C, n, 2);
}

// round 9
// speedup vs baseline: 1.6567x; 1.0997x over previous
#include <cuda_runtime.h>
#include <math.h>

#define C 64
#define MAX_N 65536
#define MAX_ETOT 2000000

// ---------------- device scratch (no allocation allowed) ----------------
__device__ int   g_deg[MAX_N];
__device__ int   g_incl[MAX_N];
__device__ int   g_bsum[256];
__device__ int   g_rowptr[MAX_N + 1];
__device__ int   g_fillptr[MAX_N];
__device__ int   g_col[MAX_ETOT];
__device__ __align__(256) float g_buf0[(size_t)MAX_N * C];
__device__ __align__(256) float g_buf1[(size_t)MAX_N * C];
__device__ __align__(256) float g_accum[(size_t)MAX_N * C];

// ---------------- CSR build ----------------

__global__ void k_init_deg(int n) {
    int i = blockIdx.x * blockDim.x + threadIdx.x;
    if (i < n) g_deg[i] = 1;                      // self loop
}

__global__ void k_count(const int* __restrict__ ei, int E) {
    int i = blockIdx.x * blockDim.x + threadIdx.x;
    if (i < E) atomicAdd(&g_deg[ei[E + i]], 1);   // dst row
}

__global__ void k_scan_block(int n) {
    __shared__ int sh[1024];
    int i = blockIdx.x * 1024 + threadIdx.x;
    int v = (i < n) ? g_deg[i] : 0;
    sh[threadIdx.x] = v;
    __syncthreads();
    #pragma unroll
    for (int off = 1; off < 1024; off <<= 1) {
        int t = (threadIdx.x >= off) ? sh[threadIdx.x - off] : 0;
        __syncthreads();
        sh[threadIdx.x] += t;
        __syncthreads();
    }
    if (i < n) g_incl[i] = sh[threadIdx.x];
    if (threadIdx.x == 1023) g_bsum[blockIdx.x] = sh[1023];
}

__global__ void k_scan_bsum(int nb) {
    __shared__ int sh[64];
    int t = threadIdx.x;
    int v = (t < nb) ? g_bsum[t] : 0;
    sh[t] = v;
    __syncthreads();
    #pragma unroll
    for (int off = 1; off < 64; off <<= 1) {
        int u = (t >= off) ? sh[t - off] : 0;
        __syncthreads();
        sh[t] += u;
        __syncthreads();
    }
    if (t < nb) g_bsum[t] = sh[t] - v;            // exclusive
}

__global__ void k_rowptr(int n, int etot) {
    int i = blockIdx.x * blockDim.x + threadIdx.x;
    if (i < n) {
        int ex = g_incl[i] - g_deg[i] + g_bsum[i >> 10];
        g_rowptr[i] = ex;
        g_fillptr[i] = ex;
    }
    if (i == 0) g_rowptr[n] = etot;
}

__global__ void k_fill(const int* __restrict__ ei, int E, int n) {
    int i = blockIdx.x * blockDim.x + threadIdx.x;
    int tot = E + n;
    if (i >= tot) return;
    int src, dst;
    if (i < E) { src = ei[i]; dst = ei[E + i]; }
    else       { src = dst = i - E; }
    int pos = atomicAdd(&g_fillptr[dst], 1);
    g_col[pos] = src;
}

// ---------------- GAT layer: 4 nodes per warp, 8 lanes (8 ch each) per node --
// All 4 groups advance one edge per warp-iteration -> every SHFL/MUFU/LDG
// warp-instruction serves 4 edges. Groups loop to the warp-max degree;
// out-of-range iterations get weight 0 to keep full-warp converged shuffles.
// Next-iteration src index is prefetched so the g_col LDG overlaps compute.
// mode: 0 = first layer (accum = x + r), 1 = middle (accum += r),
//       2 = last (out = (accum + r) * 0.25)
__global__ __launch_bounds__(256)
void k_gat(const float* __restrict__ x,
           float* __restrict__ nxt,
           float* __restrict__ out,
           const float* __restrict__ att,    // [2,64] this layer
           const float* __restrict__ bias,   // [64]
           int n, int mode) {
    const unsigned FULL = 0xffffffffu;
    int lane = threadIdx.x & 31;
    int warp = (blockIdx.x * blockDim.x + threadIdx.x) >> 5;
    int grp  = lane >> 3;        // 0..3  : which node of this warp
    int li   = lane & 7;         // 0..7  : lane within group
    bool hi  = (lane & 4) != 0;  // upper quad of group -> owns head1 score

    int node = warp * 4 + grp;
    bool nvalid = node < n;
    int safe_node = nvalid ? node : 0;

    // per-lane channels: c = li*8 + k, k = 0..7
    int cbase = li * 8;
    float a0[8], a1[8], xd[8];
    {
        float4 t0 = *(const float4*)(att + cbase);
        float4 t1 = *(const float4*)(att + cbase + 4);
        a0[0]=t0.x; a0[1]=t0.y; a0[2]=t0.z; a0[3]=t0.w;
        a0[4]=t1.x; a0[5]=t1.y; a0[6]=t1.z; a0[7]=t1.w;
        float4 u0 = *(const float4*)(att + C + cbase);
        float4 u1 = *(const float4*)(att + C + cbase + 4);
        a1[0]=u0.x; a1[1]=u0.y; a1[2]=u0.z; a1[3]=u0.w;
        a1[4]=u1.x; a1[5]=u1.y; a1[6]=u1.z; a1[7]=u1.w;
    }
    {
        size_t ro = (size_t)safe_node * C + cbase;
        float4 d0 = *(const float4*)(x + ro);
        float4 d1 = *(const float4*)(x + ro + 4);
        xd[0]=d0.x; xd[1]=d0.y; xd[2]=d0.z; xd[3]=d0.w;
        xd[4]=d1.x; xd[5]=d1.y; xd[6]=d1.z; xd[7]=d1.w;
    }

    int beg = 0, end = 0;
    if (nvalid) { beg = g_rowptr[node]; end = g_rowptr[node + 1]; }
    int deg = end - beg;
    int md = deg;
    md = max(md, __shfl_xor_sync(FULL, md, 8));
    md = max(md, __shfl_xor_sync(FULL, md, 16));

    float acc0[8], acc1[8];
    #pragma unroll
    for (int k = 0; k < 8; ++k) { acc0[k] = 0.f; acc1[k] = 0.f; }
    float s_mine = 0.f;   // denom for this quad's head (identical within quad)

    // prefetch first src index
    int src_next = (0 < deg) ? g_col[beg] : safe_node;

    for (int i = 0; i < md; ++i) {
        bool ev = (i < deg);
        int src = src_next;
        int inx = i + 1;
        src_next = (inx < deg) ? g_col[beg + inx] : safe_node;

        float xs[8];
        {
            size_t ro = (size_t)src * C + cbase;
            float4 s0 = *(const float4*)(x + ro);
            float4 s1 = *(const float4*)(x + ro + 4);
            xs[0]=s0.x; xs[1]=s0.y; xs[2]=s0.z; xs[3]=s0.w;
            xs[4]=s1.x; xs[5]=s1.y; xs[6]=s1.z; xs[7]=s1.w;
        }

        float p0 = 0.f, p1 = 0.f;
        #pragma unroll
        for (int k = 0; k < 8; ++k) {
            float t = xd[k] + xs[k];
            t = fmaxf(t, 0.2f * t);          // leaky_relu, slope 0.2
            p0 = fmaf(t, a0[k], p0);
            p1 = fmaf(t, a1[k], p1);
        }

        // group-of-8 reduce: fold heads across xor4, butterfly within quad
        float p0o = __shfl_xor_sync(FULL, p0, 4);
        float p1o = __shfl_xor_sync(FULL, p1, 4);
        float v = hi ? (p1 + p1o) : (p0 + p0o);
        v += __shfl_xor_sync(FULL, v, 2);
        v += __shfl_xor_sync(FULL, v, 1);
        // lower quad: full head0 score; upper quad: head1 score

        float w_mine = ev ? __expf(v) : 0.f;
        float w_oth  = __shfl_xor_sync(FULL, w_mine, 4);
        float w0 = hi ? w_oth  : w_mine;
        float w1 = hi ? w_mine : w_oth;

        s_mine += w_mine;
        #pragma unroll
        for (int k = 0; k < 8; ++k) {
            acc0[k] = fmaf(w0, xs[k], acc0[k]);
            acc1[k] = fmaf(w1, xs[k], acc1[k]);
        }
    }

    if (!nvalid) return;

    float s_oth = __shfl_xor_sync(FULL, s_mine, 4);
    float s0 = hi ? s_oth : s_mine;
    float s1 = hi ? s_mine : s_oth;
    float inv0 = 1.f / (s0 + 1e-16f);
    float inv1 = 1.f / (s1 + 1e-16f);

    float r[8];
    {
        float4 b0 = *(const float4*)(bias + cbase);
        float4 b1 = *(const float4*)(bias + cbase + 4);
        float bb[8] = {b0.x,b0.y,b0.z,b0.w,b1.x,b1.y,b1.z,b1.w};
        #pragma unroll
        for (int k = 0; k < 8; ++k)
            r[k] = 0.5f * fmaf(acc0[k], inv0, acc1[k] * inv1) + bb[k];
    }

    size_t o = (size_t)node * C + cbase;
    if (mode == 2) {
        float4 ac0 = *(const float4*)(g_accum + o);
        float4 ac1 = *(const float4*)(g_accum + o + 4);
        float4 o0, o1;
        o0.x = (ac0.x + r[0]) * 0.25f; o0.y = (ac0.y + r[1]) * 0.25f;
        o0.z = (ac0.z + r[2]) * 0.25f; o0.w = (ac0.w + r[3]) * 0.25f;
        o1.x = (ac1.x + r[4]) * 0.25f; o1.y = (ac1.y + r[5]) * 0.25f;
        o1.z = (ac1.z + r[6]) * 0.25f; o1.w = (ac1.w + r[7]) * 0.25f;
        *(float4*)(out + o)     = o0;
        *(float4*)(out + o + 4) = o1;
    } else {
        *(float4*)(nxt + o)     = make_float4(r[0], r[1], r[2], r[3]);
        *(float4*)(nxt + o + 4) = make_float4(r[4], r[5], r[6], r[7]);
        float4 ac0, ac1;
        if (mode == 0) {
            ac0 = make_float4(xd[0]+r[0], xd[1]+r[1], xd[2]+r[2], xd[3]+r[3]);
            ac1 = make_float4(xd[4]+r[4], xd[5]+r[5], xd[6]+r[6], xd[7]+r[7]);
        } else {
            ac0 = *(const float4*)(g_accum + o);
            ac1 = *(const float4*)(g_accum + o + 4);
            ac0.x += r[0]; ac0.y += r[1]; ac0.z += r[2]; ac0.w += r[3];
            ac1.x += r[4]; ac1.y += r[5]; ac1.z += r[6]; ac1.w += r[7];
        }
        *(float4*)(g_accum + o)     = ac0;
        *(float4*)(g_accum + o + 4) = ac1;
    }
}

// ---------------- host launcher ----------------
extern "C" void kernel_launch(void* const* d_in, const int* in_sizes, int n_in,
                              void* d_out, int out_size) {
    const float* x    = (const float*)d_in[0];   // [N, 64]
    const int*   ei   = (const int*)d_in[1];     // [2, E]
    const float* att  = (const float*)d_in[2];   // [L, 2, 64]
    const float* bias = (const float*)d_in[3];   // [L, 64]
    float* out = (float*)d_out;

    int n    = in_sizes[0] / C;
    int E    = in_sizes[1] / 2;
    int etot = E + n;

    float *buf0, *buf1;
    cudaGetSymbolAddress((void**)&buf0, g_buf0);
    cudaGetSymbolAddress((void**)&buf1, g_buf1);

    const int T = 256;
    // ---- CSR build ----
    k_init_deg<<<(n + T - 1) / T, T>>>(n);
    k_count<<<(E + T - 1) / T, T>>>(ei, E);
    int nb = (n + 1023) / 1024;
    k_scan_block<<<nb, 1024>>>(n);
    k_scan_bsum<<<1, 64>>>(nb);
    k_rowptr<<<(n + T - 1) / T, T>>>(n, etot);
    k_fill<<<(etot + T - 1) / T, T>>>(ei, E, n);

    // ---- 3 GAT layers: 256 thr = 8 warps = 32 nodes per block ----
    int gb = (n + 31) / 32;
    k_gat<<<gb, 256>>>(x,    buf0, out, att,         bias,         n, 0);
    k_gat<<<gb, 256>>>(buf0, buf1, out, att + 2 * C, bias + C,     n, 1);
    k_gat<<<gb, 256>>>(buf1, buf0, out, att + 4 * C, bias + 2 * C, n, 2);
}